// round 4
// baseline (speedup 1.0000x reference)
#include <cuda_runtime.h>

#define N_PTS 65536
#define D_DIM 512
#define K_CL  4096

#define TM 128
#define TN 128
#define TD 16
#define TS 132          // smem row stride in floats (128 + 4 pad)

__global__ __launch_bounds__(256)
void kmeans_kernel(const float* __restrict__ x,
                   const float* __restrict__ center,
                   float* __restrict__ out) {
    __shared__ float As[TD * TS];   // x tile, transposed [d][row]
    __shared__ float Bs[TD * TS];   // center tile, transposed [d][col]

    const int tid = threadIdx.x;
    const int tx = tid & 15;          // 16 col-groups of 8 centers
    const int ty = tid >> 4;          // 16 row-groups of 8 points
    const int r0 = ty * 8;
    const int c0 = tx * 8;
    const int rowblock = blockIdx.x * TM;

    float best[8];
    int   bidx[8];
#pragma unroll
    for (int i = 0; i < 8; i++) { best[i] = 3.4e38f; bidx[i] = 0; }

    for (int kt = 0; kt < K_CL; kt += TN) {
        float acc[8][8];
        float csq[8];
#pragma unroll
        for (int i = 0; i < 8; i++) {
            csq[i] = 0.0f;
#pragma unroll
            for (int j = 0; j < 8; j++) acc[i][j] = 0.0f;
        }

        for (int dt = 0; dt < D_DIM; dt += TD) {
            // ---- stage: 2048 floats per tile, 256 threads x 2 iters x float4
#pragma unroll
            for (int l = 0; l < 2; l++) {
                int idx = tid + l * 256;        // 0..511
                int row = idx >> 2;             // 0..127
                int c4  = idx & 3;
                int dbase = c4 * 4;

                float4 v = *reinterpret_cast<const float4*>(
                    x + (size_t)(rowblock + row) * D_DIM + dt + c4 * 4);
                As[(dbase + 0) * TS + row] = v.x;
                As[(dbase + 1) * TS + row] = v.y;
                As[(dbase + 2) * TS + row] = v.z;
                As[(dbase + 3) * TS + row] = v.w;

                float4 w = *reinterpret_cast<const float4*>(
                    center + (size_t)(kt + row) * D_DIM + dt + c4 * 4);
                Bs[(dbase + 0) * TS + row] = w.x;
                Bs[(dbase + 1) * TS + row] = w.y;
                Bs[(dbase + 2) * TS + row] = w.z;
                Bs[(dbase + 3) * TS + row] = w.w;
            }
            __syncthreads();

            // ---- compute: dot products + inline center squared norms
#pragma unroll
            for (int d = 0; d < TD; d++) {
                float a[8], b[8];
#pragma unroll
                for (int i = 0; i < 8; i++) a[i] = As[d * TS + r0 + i];
#pragma unroll
                for (int j = 0; j < 8; j++) b[j] = Bs[d * TS + c0 + j];
#pragma unroll
                for (int j = 0; j < 8; j++) csq[j] = fmaf(b[j], b[j], csq[j]);
#pragma unroll
                for (int i = 0; i < 8; i++)
#pragma unroll
                    for (int j = 0; j < 8; j++)
                        acc[i][j] = fmaf(a[i], b[j], acc[i][j]);
            }
            __syncthreads();
        }

        // ---- epilogue: dist = (-2*dot) + csq (x_sq is a constant per-row
        //      shift and cannot change the argmin). mul/add kept separate
        //      to stay on the reference's fp32 rounding grid.
#pragma unroll
        for (int i = 0; i < 8; i++) {
#pragma unroll
            for (int j = 0; j < 8; j++) {
                float dist = __fadd_rn(__fmul_rn(-2.0f, acc[i][j]), csq[j]);
                if (dist < best[i]) { best[i] = dist; bidx[i] = kt + c0 + j; }
            }
        }
    }

    // ---- per-row argmin across the 16 column-threads (consecutive lanes),
    //      lexicographic (dist, idx) to preserve first-occurrence semantics
#pragma unroll
    for (int i = 0; i < 8; i++) {
        float b = best[i];
        int  bi = bidx[i];
#pragma unroll
        for (int off = 8; off > 0; off >>= 1) {
            float ob = __shfl_down_sync(0xffffffffu, b, off, 16);
            int   oi = __shfl_down_sync(0xffffffffu, bi, off, 16);
            if (ob < b || (ob == b && oi < bi)) { b = ob; bi = oi; }
        }
        // KEY CHANGE: output buffer is validated as float32 — write the index
        // as a float value (exactly representable for k < 2^24).
        if (tx == 0) out[rowblock + r0 + i] = (float)bi;
    }
}

extern "C" void kernel_launch(void* const* d_in, const int* in_sizes, int n_in,
                              void* d_out, int out_size) {
    const float* x      = (const float*)d_in[0];
    const float* center = (const float*)d_in[1];
    // x is the strictly larger array (N*D vs K*D) whether sizes are elements
    // or bytes; swap if the harness orders them the other way.
    if (n_in >= 2 && in_sizes[0] < in_sizes[1]) {
        const float* tmp = x; x = center; center = tmp;
    }
    float* out = (float*)d_out;

    kmeans_kernel<<<N_PTS / TM, 256>>>(x, center, out);
}

// round 7
// speedup vs baseline: 1.0940x; 1.0940x over previous
#include <cuda_runtime.h>

#define N_PTS 65536
#define D_DIM 512
#define K_CL  4096

#define TM 128
#define TN 128
#define TD 16
#define AS_STRIDE 130   // ull units per d-row: 128 pairs + 2 pad (16B-aligned rows)
#define BS_STRIDE 132   // float units per d-row: 128 + 4 pad (16B-aligned rows)

typedef unsigned long long ull;

// Packed dual-lane fp32 FMA (sm_103a): acc.{lo,hi} += a.{lo,hi} * b.{lo,hi}
__device__ __forceinline__ void ffma2(ull &acc, ull a2, ull b2) {
    asm("fma.rn.f32x2 %0, %1, %2, %0;" : "+l"(acc) : "l"(a2), "l"(b2));
}

__global__ __launch_bounds__(256, 2)
void kmeans_kernel(const float* __restrict__ x,
                   const float* __restrict__ center,
                   float* __restrict__ out) {
    // A tile: transposed [d][row], each x value duplicated into a float2{v,v}
    // so it can feed fma.rn.f32x2 directly (both lanes need the same a).
    __shared__ ull   As2[TD * AS_STRIDE];
    __shared__ float Bs[TD * BS_STRIDE];

    const int tid = threadIdx.x;
    const int tx = tid & 15;          // 16 col-groups of 8 centers
    const int ty = tid >> 4;          // 16 row-groups of 8 points
    const int r0 = ty * 8;
    const int c0 = tx * 8;
    const int rowblock = blockIdx.x * TM;

    float best[8];
    int   bidx[8];
#pragma unroll
    for (int i = 0; i < 8; i++) { best[i] = 3.4e38f; bidx[i] = 0; }

    for (int kt = 0; kt < K_CL; kt += TN) {
        ull acc[8][4];    // 8 rows x 4 packed col-pairs (cols c0..c0+7)
        ull csq2[4];      // packed center squared-norms for the same col-pairs
#pragma unroll
        for (int i = 0; i < 8; i++)
#pragma unroll
            for (int j = 0; j < 4; j++) acc[i][j] = 0ull;
#pragma unroll
        for (int j = 0; j < 4; j++) csq2[j] = 0ull;

        for (int dt = 0; dt < D_DIM; dt += TD) {
            // ---- stage tiles
#pragma unroll
            for (int l = 0; l < 2; l++) {
                int idx = tid + l * 256;        // 0..511 float4 slots
                int row = idx >> 2;             // 0..127
                int c4  = idx & 3;
                int dbase = c4 * 4;

                float4 v = *reinterpret_cast<const float4*>(
                    x + (size_t)(rowblock + row) * D_DIM + dt + c4 * 4);
                float vv[4] = {v.x, v.y, v.z, v.w};
#pragma unroll
                for (int t = 0; t < 4; t++) {
                    float2 p = make_float2(vv[t], vv[t]);
                    *reinterpret_cast<float2*>(&As2[(dbase + t) * AS_STRIDE + row]) = p;
                }

                float4 w = *reinterpret_cast<const float4*>(
                    center + (size_t)(kt + row) * D_DIM + dt + c4 * 4);
                Bs[(dbase + 0) * BS_STRIDE + row] = w.x;
                Bs[(dbase + 1) * BS_STRIDE + row] = w.y;
                Bs[(dbase + 2) * BS_STRIDE + row] = w.z;
                Bs[(dbase + 3) * BS_STRIDE + row] = w.w;
            }
            __syncthreads();

            // ---- compute: per d-step 36 FFMA2 + 6 LDS.128
#pragma unroll
            for (int d = 0; d < TD; d++) {
                ull a2[8], b2[4];
#pragma unroll
                for (int i = 0; i < 8; i++)
                    a2[i] = As2[d * AS_STRIDE + r0 + i];
#pragma unroll
                for (int j = 0; j < 4; j++)
                    b2[j] = *reinterpret_cast<const ull*>(
                        &Bs[d * BS_STRIDE + c0 + 2 * j]);
#pragma unroll
                for (int j = 0; j < 4; j++) ffma2(csq2[j], b2[j], b2[j]);
#pragma unroll
                for (int i = 0; i < 8; i++)
#pragma unroll
                    for (int j = 0; j < 4; j++)
                        ffma2(acc[i][j], a2[i], b2[j]);
            }
            __syncthreads();
        }

        // ---- epilogue: dist = (-2*dot) + csq per column; each packed lane is
        //      the same sequential fma chain as the scalar kernel -> identical
        //      rounding grid as the passing R4 kernel.
        float csqs[8];
#pragma unroll
        for (int j = 0; j < 4; j++) {
            csqs[2 * j]     = __uint_as_float((unsigned)(csq2[j] & 0xffffffffull));
            csqs[2 * j + 1] = __uint_as_float((unsigned)(csq2[j] >> 32));
        }
#pragma unroll
        for (int i = 0; i < 8; i++) {
#pragma unroll
            for (int j = 0; j < 8; j++) {
                ull p = acc[i][j >> 1];
                float dot = (j & 1) ? __uint_as_float((unsigned)(p >> 32))
                                    : __uint_as_float((unsigned)(p & 0xffffffffull));
                float dist = __fadd_rn(__fmul_rn(-2.0f, dot), csqs[j]);
                if (dist < best[i]) { best[i] = dist; bidx[i] = kt + c0 + j; }
            }
        }
    }

    // ---- per-row argmin across the 16 column-threads, lexicographic (dist, idx)
#pragma unroll
    for (int i = 0; i < 8; i++) {
        float b = best[i];
        int  bi = bidx[i];
#pragma unroll
        for (int off = 8; off > 0; off >>= 1) {
            float ob = __shfl_down_sync(0xffffffffu, b, off, 16);
            int   oi = __shfl_down_sync(0xffffffffu, bi, off, 16);
            if (ob < b || (ob == b && oi < bi)) { b = ob; bi = oi; }
        }
        if (tx == 0) out[rowblock + r0 + i] = (float)bi;   // float32 output
    }
}

extern "C" void kernel_launch(void* const* d_in, const int* in_sizes, int n_in,
                              void* d_out, int out_size) {
    const float* x      = (const float*)d_in[0];
    const float* center = (const float*)d_in[1];
    if (n_in >= 2 && in_sizes[0] < in_sizes[1]) {
        const float* tmp = x; x = center; center = tmp;
    }
    float* out = (float*)d_out;

    kmeans_kernel<<<N_PTS / TM, 256>>>(x, center, out);
}

// round 13
// speedup vs baseline: 5.9725x; 5.4594x over previous
#include <cuda_runtime.h>
#include <cuda_bf16.h>
#include <cstdint>

#define N_PTS 65536
#define D_DIM 512
#define K_CL  4096
#define MARGIN_T 0.6f

typedef unsigned long long ull;

// ---------------- scratch ----------------------------------------------------
__device__ __nv_bfloat16 g_chi[K_CL * D_DIM];
__device__ float g_csq[K_CL];
__device__ int   g_nflag;
__device__ int   g_flag[N_PTS];
__device__ ull   g_best[N_PTS];

// ---------------- PTX helpers ------------------------------------------------
__device__ __forceinline__ uint32_t smem_u32(const void* p) {
    uint32_t a;
    asm("{ .reg .u64 t; cvta.to.shared.u64 t, %1; cvt.u32.u64 %0, t; }"
        : "=r"(a) : "l"(p));
    return a;
}
__device__ __forceinline__ void ldm_x4(uint32_t* r, uint32_t addr) {
    asm volatile("ldmatrix.sync.aligned.m8n8.x4.shared.b16 {%0,%1,%2,%3}, [%4];"
        : "=r"(r[0]), "=r"(r[1]), "=r"(r[2]), "=r"(r[3]) : "r"(addr));
}
__device__ __forceinline__ void mma16816(float* c, const uint32_t* a, const uint32_t* b) {
    asm volatile("mma.sync.aligned.m16n8k16.row.col.f32.bf16.bf16.f32 "
        "{%0,%1,%2,%3}, {%4,%5,%6,%7}, {%8,%9}, {%0,%1,%2,%3};"
        : "+f"(c[0]), "+f"(c[1]), "+f"(c[2]), "+f"(c[3])
        : "r"(a[0]), "r"(a[1]), "r"(a[2]), "r"(a[3]), "r"(b[0]), "r"(b[1]));
}
__device__ __forceinline__ void cpasync16(uint32_t dst, const void* src) {
    asm volatile("cp.async.cg.shared.global [%0], [%1], 16;"
        :: "r"(dst), "l"(src) : "memory");
}
#define CP_COMMIT() asm volatile("cp.async.commit_group;" ::: "memory")
#define CP_WAIT0()  asm volatile("cp.async.wait_group 0;" ::: "memory")
#define CP_WAIT1()  asm volatile("cp.async.wait_group 1;" ::: "memory")

// ordered-uint encoding: monotone in float value
__device__ __forceinline__ ull packdi(float d, int idx) {
    unsigned b = __float_as_uint(d);
    b = (b & 0x80000000u) ? ~b : (b | 0x80000000u);
    return ((ull)b << 32) | (unsigned)idx;
}
// merge top-2 (lexicographic on (dist, idx) for the winner)
__device__ __forceinline__ void merge2(float& b1, int& i1, float& b2,
                                       float ob1, int oi1, float ob2) {
    if (ob1 < b1 || (ob1 == b1 && oi1 < i1)) {
        b2 = fminf(b1, ob2); b1 = ob1; i1 = oi1;
    } else {
        b2 = fminf(b2, ob1);
    }
}

// ---------------- precompute -------------------------------------------------
__global__ void cvt_c_kernel(const float* __restrict__ src) {
    int i = blockIdx.x * blockDim.x + threadIdx.x;          // float4 index
    if (i == 0) g_nflag = 0;
    float4 v = reinterpret_cast<const float4*>(src)[i];
    __nv_bfloat162* p = reinterpret_cast<__nv_bfloat162*>(g_chi + 4 * (size_t)i);
    p[0] = __floats2bfloat162_rn(v.x, v.y);
    p[1] = __floats2bfloat162_rn(v.z, v.w);
}
__global__ void csq_kernel(const float* __restrict__ center) {
    int k = blockIdx.x;
    float4 v = reinterpret_cast<const float4*>(center + (size_t)k * D_DIM)[threadIdx.x];
    float s = v.x * v.x + v.y * v.y + v.z * v.z + v.w * v.w;
#pragma unroll
    for (int off = 16; off > 0; off >>= 1)
        s += __shfl_down_sync(0xffffffffu, s, off);
    __shared__ float p[4];
    if ((threadIdx.x & 31) == 0) p[threadIdx.x >> 5] = s;
    __syncthreads();
    if (threadIdx.x == 0) g_csq[k] = (p[0] + p[1]) + (p[2] + p[3]);
}

// ---------------- main HMMA kernel ------------------------------------------
#define RA 520                      // A smem row stride (bf16 units)
#define RB 72                       // B smem row stride (bf16 units)
#define A_BYTES   (128 * RA * 2)    // 133120
#define BBUF_BYTES (128 * RB * 2)   // 18432
#define SMEM_DYN  (A_BYTES + 2 * BBUF_BYTES)   // 169984

__global__ __launch_bounds__(256)
void kmeans_mma_kernel(const float* __restrict__ x, float* __restrict__ out) {
    extern __shared__ char smraw[];
    const uint32_t smA = smem_u32(smraw);
    const uint32_t smB0 = smA + A_BYTES;

    __shared__ float red1[128][4], red2[128][4];
    __shared__ int   redi[128][4];

    const int tid  = threadIdx.x;
    const int lane = tid & 31;
    const int warp = tid >> 5;
    const int wm = warp >> 2;         // 0..1 (M)
    const int wn = warp & 3;          // 0..3 (N)
    const int g = lane >> 2, t = lane & 3;
    const int rowbase = blockIdx.x * 128;

    // ---- load A (128 rows x 512 fp32 -> bf16 smem), once ----
    {
        int row = tid >> 1, half = tid & 1;
        const float4* src = reinterpret_cast<const float4*>(
            x + (size_t)(rowbase + row) * D_DIM + half * 256);
        uint32_t dst = smA + (row * RA + half * 256) * 2;
#pragma unroll 8
        for (int j = 0; j < 64; j++) {
            float4 v = src[j];
            __nv_bfloat162 p0 = __floats2bfloat162_rn(v.x, v.y);
            __nv_bfloat162 p1 = __floats2bfloat162_rn(v.z, v.w);
            uint2 u;
            u.x = *reinterpret_cast<uint32_t*>(&p0);
            u.y = *reinterpret_cast<uint32_t*>(&p1);
            asm volatile("st.shared.v2.b32 [%0], {%1, %2};"
                :: "r"(dst + j * 8), "r"(u.x), "r"(u.y) : "memory");
        }
    }

    float best1[8], best2[8]; int bidx[8];
#pragma unroll
    for (int r = 0; r < 8; r++) { best1[r] = 3.4e38f; best2[r] = 3.4e38f; bidx[r] = 0; }

    const int nrow = tid >> 1, seg = tid & 1;     // B stage mapping

    for (int kt = 0; kt < 32; kt++) {
        const int ktbase = kt * 128;
        float acc[4][4][4];
#pragma unroll
        for (int mt = 0; mt < 4; mt++)
#pragma unroll
            for (int nt = 0; nt < 4; nt++)
#pragma unroll
                for (int e = 0; e < 4; e++) acc[mt][nt][e] = 0.0f;

        // prologue: stage B chunk 0
        {
            const __nv_bfloat16* src = g_chi + (size_t)(ktbase + nrow) * D_DIM + seg * 32;
            uint32_t dst = smB0 + (nrow * RB + seg * 32) * 2;
#pragma unroll
            for (int j = 0; j < 4; j++) cpasync16(dst + j * 16, src + j * 8);
            CP_COMMIT();
        }

        for (int dc = 0; dc < 8; dc++) {
            if (dc < 7) {
                const __nv_bfloat16* src =
                    g_chi + (size_t)(ktbase + nrow) * D_DIM + (dc + 1) * 64 + seg * 32;
                uint32_t dst = smB0 + ((dc + 1) & 1) * BBUF_BYTES + (nrow * RB + seg * 32) * 2;
#pragma unroll
                for (int j = 0; j < 4; j++) cpasync16(dst + j * 16, src + j * 8);
                CP_COMMIT();
                CP_WAIT1();
            } else {
                CP_WAIT0();
            }
            __syncthreads();

            const uint32_t smB = smB0 + (dc & 1) * BBUF_BYTES;
            const int r8 = lane & 7, sub = lane >> 3;
#pragma unroll
            for (int ks = 0; ks < 4; ks++) {
                const int kc = dc * 64 + ks * 16;
                uint32_t af[4][4], bf_[4][2];
#pragma unroll
                for (int mt = 0; mt < 4; mt++) {
                    int row = wm * 64 + mt * 16 + (sub & 1) * 8 + r8;
                    int col = kc + (sub >> 1) * 8;
                    ldm_x4(af[mt], smA + (row * RA + col) * 2);
                }
#pragma unroll
                for (int p = 0; p < 2; p++) {
                    int n = wn * 32 + p * 16 + (sub >> 1) * 8 + r8;
                    int col = ks * 16 + (sub & 1) * 8;
                    uint32_t r4[4];
                    ldm_x4(r4, smB + (n * RB + col) * 2);
                    bf_[2 * p][0] = r4[0]; bf_[2 * p][1] = r4[1];
                    bf_[2 * p + 1][0] = r4[2]; bf_[2 * p + 1][1] = r4[3];
                }
#pragma unroll
                for (int mt = 0; mt < 4; mt++)
#pragma unroll
                    for (int nt = 0; nt < 4; nt++)
                        mma16816(acc[mt][nt], af[mt], bf_[nt]);
            }
            __syncthreads();
        }

        // ---- epilogue scan: ascending n, strict < ----
#pragma unroll
        for (int mt = 0; mt < 4; mt++)
#pragma unroll
            for (int half = 0; half < 2; half++) {
                const int ridx = mt * 2 + half;
                float b1 = best1[ridx], b2 = best2[ridx]; int bi = bidx[ridx];
#pragma unroll
                for (int nt = 0; nt < 4; nt++)
#pragma unroll
                    for (int e = 0; e < 2; e++) {
                        float dot = acc[mt][nt][half * 2 + e];
                        int n = ktbase + wn * 32 + nt * 8 + 2 * t + e;
                        float dist = fmaf(-2.0f, dot, __ldg(&g_csq[n]));
                        if (dist < b1) { b2 = b1; b1 = dist; bi = n; }
                        else if (dist < b2) { b2 = dist; }
                    }
                best1[ridx] = b1; best2[ridx] = b2; bidx[ridx] = bi;
            }
    }

    // ---- quad reduce (lanes sharing rows) + cross-warp reduce ----
#pragma unroll
    for (int r = 0; r < 8; r++) {
        float b1 = best1[r], b2 = best2[r]; int i1 = bidx[r];
#pragma unroll
        for (int off = 1; off < 4; off <<= 1) {
            float ob1 = __shfl_xor_sync(0xffffffffu, b1, off);
            int   oi1 = __shfl_xor_sync(0xffffffffu, i1, off);
            float ob2 = __shfl_xor_sync(0xffffffffu, b2, off);
            merge2(b1, i1, b2, ob1, oi1, ob2);
        }
        if (t == 0) {
            int rl = wm * 64 + (r >> 1) * 16 + (r & 1) * 8 + g;
            red1[rl][wn] = b1; red2[rl][wn] = b2; redi[rl][wn] = i1;
        }
    }
    __syncthreads();
    if (tid < 128) {
        float b1 = red1[tid][0], b2 = red2[tid][0]; int i1 = redi[tid][0];
#pragma unroll
        for (int w = 1; w < 4; w++)
            merge2(b1, i1, b2, red1[tid][w], redi[tid][w], red2[tid][w]);
        out[rowbase + tid] = (float)i1;
        if (b2 - b1 < MARGIN_T) {
            int s = atomicAdd(&g_nflag, 1);
            g_flag[s] = rowbase + tid;
            g_best[rowbase + tid] = ~0ull;
        }
    }
}

// ---------------- exact fp32 rescue (center-parallel) ------------------------
__global__ __launch_bounds__(256)
void rescue_kernel(const float* __restrict__ x, const float* __restrict__ center) {
    __shared__ float As[16 * 132], Bs[16 * 132];
    __shared__ int rows[128];
    const int nf = g_nflag;
    const int nchunks = (nf + 127) >> 7;
    const int tid = threadIdx.x;
    const int tx = tid & 15, ty = tid >> 4;
    const int r0 = ty * 8, c0 = tx * 8;
    const int kb = blockIdx.x * 128;

    for (int rc = blockIdx.y; rc < nchunks; rc += 64) {
        __syncthreads();
        if (tid < 128) {
            int slot = rc * 128 + tid;
            rows[tid] = g_flag[slot < nf ? slot : nf - 1];
        }
        __syncthreads();

        float acc[8][8];
#pragma unroll
        for (int i = 0; i < 8; i++)
#pragma unroll
            for (int j = 0; j < 8; j++) acc[i][j] = 0.0f;

        for (int dt = 0; dt < D_DIM; dt += 16) {
#pragma unroll
            for (int l = 0; l < 2; l++) {
                int idx = tid + l * 256;
                int rr = idx >> 2, c4 = idx & 3, dbase = c4 * 4;
                float4 v = *reinterpret_cast<const float4*>(
                    x + (size_t)rows[rr] * D_DIM + dt + c4 * 4);
                As[(dbase + 0) * 132 + rr] = v.x; As[(dbase + 1) * 132 + rr] = v.y;
                As[(dbase + 2) * 132 + rr] = v.z; As[(dbase + 3) * 132 + rr] = v.w;
                float4 w = *reinterpret_cast<const float4*>(
                    center + (size_t)(kb + rr) * D_DIM + dt + c4 * 4);
                Bs[(dbase + 0) * 132 + rr] = w.x; Bs[(dbase + 1) * 132 + rr] = w.y;
                Bs[(dbase + 2) * 132 + rr] = w.z; Bs[(dbase + 3) * 132 + rr] = w.w;
            }
            __syncthreads();
#pragma unroll
            for (int d = 0; d < 16; d++) {
                float a[8], b[8];
#pragma unroll
                for (int i = 0; i < 8; i++) a[i] = As[d * 132 + r0 + i];
#pragma unroll
                for (int j = 0; j < 8; j++) b[j] = Bs[d * 132 + c0 + j];
#pragma unroll
                for (int i = 0; i < 8; i++)
#pragma unroll
                    for (int j = 0; j < 8; j++)
                        acc[i][j] = fmaf(a[i], b[j], acc[i][j]);
            }
            __syncthreads();
        }
#pragma unroll
        for (int i = 0; i < 8; i++) {
            float b = 3.4e38f; int bi = 0;
#pragma unroll
            for (int j = 0; j < 8; j++) {
                float dist = fmaf(-2.0f, acc[i][j], __ldg(&g_csq[kb + c0 + j]));
                if (dist < b) { b = dist; bi = kb + c0 + j; }
            }
            atomicMin(&g_best[rows[r0 + i]], packdi(b, bi));
        }
    }
}

__global__ void writeback_kernel(float* __restrict__ out) {
    const int nf = g_nflag;
    for (int s = blockIdx.x * 256 + threadIdx.x; s < nf; s += 64 * 256) {
        int row = g_flag[s];
        out[row] = (float)(unsigned)(g_best[row] & 0xffffffffull);
    }
}

// ---------------- launch -----------------------------------------------------
extern "C" void kernel_launch(void* const* d_in, const int* in_sizes, int n_in,
                              void* d_out, int out_size) {
    const float* x      = (const float*)d_in[0];
    const float* center = (const float*)d_in[1];
    if (n_in >= 2 && in_sizes[0] < in_sizes[1]) {
        const float* tmp = x; x = center; center = tmp;
    }
    float* out = (float*)d_out;

    cudaFuncSetAttribute(kmeans_mma_kernel,
                         cudaFuncAttributeMaxDynamicSharedMemorySize, SMEM_DYN);

    cvt_c_kernel<<<(K_CL * (D_DIM / 4)) / 256, 256>>>(center);
    csq_kernel<<<K_CL, 128>>>(center);
    kmeans_mma_kernel<<<N_PTS / 128, 256, SMEM_DYN>>>(x, out);
    rescue_kernel<<<dim3(32, 64), 256>>>(x, center);
    writeback_kernel<<<64, 256>>>(out);
}

// round 14
// speedup vs baseline: 6.6660x; 1.1161x over previous
#include <cuda_runtime.h>
#include <cuda_fp16.h>
#include <cstdint>

#define N_PTS 65536
#define D_DIM 512
#define K_CL  4096
#define MARGIN_T 0.2f

typedef unsigned long long ull;

// ---------------- scratch ----------------------------------------------------
__device__ __half g_chi[K_CL * D_DIM];
__device__ float g_csq[K_CL];
__device__ int   g_nflag;
__device__ int   g_flag[N_PTS];
__device__ ull   g_best[N_PTS];

// ---------------- PTX helpers ------------------------------------------------
__device__ __forceinline__ uint32_t smem_u32(const void* p) {
    uint32_t a;
    asm("{ .reg .u64 t; cvta.to.shared.u64 t, %1; cvt.u32.u64 %0, t; }"
        : "=r"(a) : "l"(p));
    return a;
}
__device__ __forceinline__ void ldm_x4(uint32_t* r, uint32_t addr) {
    asm volatile("ldmatrix.sync.aligned.m8n8.x4.shared.b16 {%0,%1,%2,%3}, [%4];"
        : "=r"(r[0]), "=r"(r[1]), "=r"(r[2]), "=r"(r[3]) : "r"(addr));
}
__device__ __forceinline__ void mma16816(float* c, const uint32_t* a, const uint32_t* b) {
    asm volatile("mma.sync.aligned.m16n8k16.row.col.f32.f16.f16.f32 "
        "{%0,%1,%2,%3}, {%4,%5,%6,%7}, {%8,%9}, {%0,%1,%2,%3};"
        : "+f"(c[0]), "+f"(c[1]), "+f"(c[2]), "+f"(c[3])
        : "r"(a[0]), "r"(a[1]), "r"(a[2]), "r"(a[3]), "r"(b[0]), "r"(b[1]));
}
__device__ __forceinline__ void cpasync16(uint32_t dst, const void* src) {
    asm volatile("cp.async.cg.shared.global [%0], [%1], 16;"
        :: "r"(dst), "l"(src) : "memory");
}
#define CP_COMMIT() asm volatile("cp.async.commit_group;" ::: "memory")
#define CP_WAIT0()  asm volatile("cp.async.wait_group 0;" ::: "memory")
#define CP_WAIT1()  asm volatile("cp.async.wait_group 1;" ::: "memory")

// ordered-uint encoding: monotone in float value
__device__ __forceinline__ ull packdi(float d, int idx) {
    unsigned b = __float_as_uint(d);
    b = (b & 0x80000000u) ? ~b : (b | 0x80000000u);
    return ((ull)b << 32) | (unsigned)idx;
}
__device__ __forceinline__ void merge2(float& b1, int& i1, float& b2,
                                       float ob1, int oi1, float ob2) {
    if (ob1 < b1 || (ob1 == b1 && oi1 < i1)) {
        b2 = fminf(b1, ob2); b1 = ob1; i1 = oi1;
    } else {
        b2 = fminf(b2, ob1);
    }
}

// ---------------- precompute -------------------------------------------------
__global__ void cvt_c_kernel(const float* __restrict__ src) {
    int i = blockIdx.x * blockDim.x + threadIdx.x;          // float4 index
    if (i == 0) g_nflag = 0;
    float4 v = reinterpret_cast<const float4*>(src)[i];
    __half2* p = reinterpret_cast<__half2*>(g_chi + 4 * (size_t)i);
    p[0] = __floats2half2_rn(v.x, v.y);
    p[1] = __floats2half2_rn(v.z, v.w);
}
__global__ void csq_kernel(const float* __restrict__ center) {
    int k = blockIdx.x;
    float4 v = reinterpret_cast<const float4*>(center + (size_t)k * D_DIM)[threadIdx.x];
    float s = v.x * v.x + v.y * v.y + v.z * v.z + v.w * v.w;
#pragma unroll
    for (int off = 16; off > 0; off >>= 1)
        s += __shfl_down_sync(0xffffffffu, s, off);
    __shared__ float p[4];
    if ((threadIdx.x & 31) == 0) p[threadIdx.x >> 5] = s;
    __syncthreads();
    if (threadIdx.x == 0) g_csq[k] = (p[0] + p[1]) + (p[2] + p[3]);
}

// ---------------- main HMMA kernel (TM=64, 2 CTA/SM) -------------------------
#define TM 64
#define RA 520                      // A smem row stride (fp16 units)
#define RB 72                       // B smem row stride (fp16 units)
#define A_BYTES    (TM * RA * 2)    // 66560
#define BBUF_BYTES (128 * RB * 2)   // 18432
#define SMEM_DYN   (A_BYTES + 2 * BBUF_BYTES)   // 103424

__global__ __launch_bounds__(256, 2)
void kmeans_mma_kernel(const float* __restrict__ x, float* __restrict__ out) {
    extern __shared__ char smraw[];
    const uint32_t smA = smem_u32(smraw);
    const uint32_t smB0 = smA + A_BYTES;

    __shared__ float red1[TM][4], red2[TM][4];
    __shared__ int   redi[TM][4];

    const int tid  = threadIdx.x;
    const int lane = tid & 31;
    const int warp = tid >> 5;
    const int wm = warp >> 2;         // 0..1 (M halves of 32 rows)
    const int wn = warp & 3;          // 0..3 (N)
    const int g = lane >> 2, t = lane & 3;
    const int rowbase = blockIdx.x * TM;

    // ---- load A (64 rows x 512 fp32 -> fp16 smem), once ----
    {
        int row = tid >> 2, q = tid & 3;        // 4 threads per row, 128 floats each
        const float4* src = reinterpret_cast<const float4*>(
            x + (size_t)(rowbase + row) * D_DIM + q * 128);
        uint32_t dst = smA + (row * RA + q * 128) * 2;
#pragma unroll 8
        for (int j = 0; j < 32; j++) {
            float4 v = src[j];
            __half2 p0 = __floats2half2_rn(v.x, v.y);
            __half2 p1 = __floats2half2_rn(v.z, v.w);
            uint2 u;
            u.x = *reinterpret_cast<uint32_t*>(&p0);
            u.y = *reinterpret_cast<uint32_t*>(&p1);
            asm volatile("st.shared.v2.b32 [%0], {%1, %2};"
                :: "r"(dst + j * 8), "r"(u.x), "r"(u.y) : "memory");
        }
    }

    float best1[4], best2[4]; int bidx[4];
#pragma unroll
    for (int r = 0; r < 4; r++) { best1[r] = 3.4e38f; best2[r] = 3.4e38f; bidx[r] = 0; }

    const int nrow = tid >> 1, seg = tid & 1;     // B stage mapping

    for (int kt = 0; kt < 32; kt++) {
        const int ktbase = kt * 128;
        float acc[2][4][4];
#pragma unroll
        for (int mt = 0; mt < 2; mt++)
#pragma unroll
            for (int nt = 0; nt < 4; nt++)
#pragma unroll
                for (int e = 0; e < 4; e++) acc[mt][nt][e] = 0.0f;

        // prologue: stage B chunk 0
        {
            const __half* src = g_chi + (size_t)(ktbase + nrow) * D_DIM + seg * 32;
            uint32_t dst = smB0 + (nrow * RB + seg * 32) * 2;
#pragma unroll
            for (int j = 0; j < 4; j++) cpasync16(dst + j * 16, src + j * 8);
            CP_COMMIT();
        }

        for (int dc = 0; dc < 8; dc++) {
            if (dc < 7) {
                const __half* src =
                    g_chi + (size_t)(ktbase + nrow) * D_DIM + (dc + 1) * 64 + seg * 32;
                uint32_t dst = smB0 + ((dc + 1) & 1) * BBUF_BYTES + (nrow * RB + seg * 32) * 2;
#pragma unroll
                for (int j = 0; j < 4; j++) cpasync16(dst + j * 16, src + j * 8);
                CP_COMMIT();
                CP_WAIT1();
            } else {
                CP_WAIT0();
            }
            __syncthreads();

            const uint32_t smB = smB0 + (dc & 1) * BBUF_BYTES;
            const int r8 = lane & 7, sub = lane >> 3;
#pragma unroll
            for (int ks = 0; ks < 4; ks++) {
                const int kc = dc * 64 + ks * 16;
                uint32_t af[2][4], bf_[4][2];
#pragma unroll
                for (int mt = 0; mt < 2; mt++) {
                    int row = wm * 32 + mt * 16 + (sub & 1) * 8 + r8;
                    int col = kc + (sub >> 1) * 8;
                    ldm_x4(af[mt], smA + (row * RA + col) * 2);
                }
#pragma unroll
                for (int p = 0; p < 2; p++) {
                    int n = wn * 32 + p * 16 + (sub >> 1) * 8 + r8;
                    int col = ks * 16 + (sub & 1) * 8;
                    uint32_t r4[4];
                    ldm_x4(r4, smB + (n * RB + col) * 2);
                    bf_[2 * p][0] = r4[0]; bf_[2 * p][1] = r4[1];
                    bf_[2 * p + 1][0] = r4[2]; bf_[2 * p + 1][1] = r4[3];
                }
#pragma unroll
                for (int mt = 0; mt < 2; mt++)
#pragma unroll
                    for (int nt = 0; nt < 4; nt++)
                        mma16816(acc[mt][nt], af[mt], bf_[nt]);
            }
            __syncthreads();
        }

        // ---- epilogue scan: ascending n, strict < ----
#pragma unroll
        for (int mt = 0; mt < 2; mt++)
#pragma unroll
            for (int half = 0; half < 2; half++) {
                const int ridx = mt * 2 + half;
                float b1 = best1[ridx], b2 = best2[ridx]; int bi = bidx[ridx];
#pragma unroll
                for (int nt = 0; nt < 4; nt++)
#pragma unroll
                    for (int e = 0; e < 2; e++) {
                        float dot = acc[mt][nt][half * 2 + e];
                        int n = ktbase + wn * 32 + nt * 8 + 2 * t + e;
                        float dist = fmaf(-2.0f, dot, __ldg(&g_csq[n]));
                        if (dist < b1) { b2 = b1; b1 = dist; bi = n; }
                        else if (dist < b2) { b2 = dist; }
                    }
                best1[ridx] = b1; best2[ridx] = b2; bidx[ridx] = bi;
            }
    }

    // ---- quad reduce (lanes sharing rows) + cross-warp reduce ----
#pragma unroll
    for (int r = 0; r < 4; r++) {
        float b1 = best1[r], b2 = best2[r]; int i1 = bidx[r];
#pragma unroll
        for (int off = 1; off < 4; off <<= 1) {
            float ob1 = __shfl_xor_sync(0xffffffffu, b1, off);
            int   oi1 = __shfl_xor_sync(0xffffffffu, i1, off);
            float ob2 = __shfl_xor_sync(0xffffffffu, b2, off);
            merge2(b1, i1, b2, ob1, oi1, ob2);
        }
        if (t == 0) {
            int rl = wm * 32 + (r >> 1) * 16 + (r & 1) * 8 + g;
            red1[rl][wn] = b1; red2[rl][wn] = b2; redi[rl][wn] = i1;
        }
    }
    __syncthreads();
    if (tid < TM) {
        float b1 = red1[tid][0], b2 = red2[tid][0]; int i1 = redi[tid][0];
#pragma unroll
        for (int w = 1; w < 4; w++)
            merge2(b1, i1, b2, red1[tid][w], redi[tid][w], red2[tid][w]);
        out[rowbase + tid] = (float)i1;
        if (b2 - b1 < MARGIN_T) {
            int s = atomicAdd(&g_nflag, 1);
            g_flag[s] = rowbase + tid;
            g_best[rowbase + tid] = ~0ull;
        }
    }
}

// ---------------- exact fp32 rescue (center-parallel) ------------------------
__global__ __launch_bounds__(256)
void rescue_kernel(const float* __restrict__ x, const float* __restrict__ center) {
    __shared__ float As[16 * 132], Bs[16 * 132];
    __shared__ int rows[128];
    const int nf = g_nflag;
    const int nchunks = (nf + 127) >> 7;
    const int tid = threadIdx.x;
    const int tx = tid & 15, ty = tid >> 4;
    const int r0 = ty * 8, c0 = tx * 8;
    const int kb = blockIdx.x * 128;

    for (int rc = blockIdx.y; rc < nchunks; rc += 64) {
        __syncthreads();
        if (tid < 128) {
            int slot = rc * 128 + tid;
            rows[tid] = g_flag[slot < nf ? slot : nf - 1];
        }
        __syncthreads();

        float acc[8][8];
#pragma unroll
        for (int i = 0; i < 8; i++)
#pragma unroll
            for (int j = 0; j < 8; j++) acc[i][j] = 0.0f;

        for (int dt = 0; dt < D_DIM; dt += 16) {
#pragma unroll
            for (int l = 0; l < 2; l++) {
                int idx = tid + l * 256;
                int rr = idx >> 2, c4 = idx & 3, dbase = c4 * 4;
                float4 v = *reinterpret_cast<const float4*>(
                    x + (size_t)rows[rr] * D_DIM + dt + c4 * 4);
                As[(dbase + 0) * 132 + rr] = v.x; As[(dbase + 1) * 132 + rr] = v.y;
                As[(dbase + 2) * 132 + rr] = v.z; As[(dbase + 3) * 132 + rr] = v.w;
                float4 w = *reinterpret_cast<const float4*>(
                    center + (size_t)(kb + rr) * D_DIM + dt + c4 * 4);
                Bs[(dbase + 0) * 132 + rr] = w.x; Bs[(dbase + 1) * 132 + rr] = w.y;
                Bs[(dbase + 2) * 132 + rr] = w.z; Bs[(dbase + 3) * 132 + rr] = w.w;
            }
            __syncthreads();
#pragma unroll
            for (int d = 0; d < 16; d++) {
                float a[8], b[8];
#pragma unroll
                for (int i = 0; i < 8; i++) a[i] = As[d * 132 + r0 + i];
#pragma unroll
                for (int j = 0; j < 8; j++) b[j] = Bs[d * 132 + c0 + j];
#pragma unroll
                for (int i = 0; i < 8; i++)
#pragma unroll
                    for (int j = 0; j < 8; j++)
                        acc[i][j] = fmaf(a[i], b[j], acc[i][j]);
            }
            __syncthreads();
        }
#pragma unroll
        for (int i = 0; i < 8; i++) {
            float b = 3.4e38f; int bi = 0;
#pragma unroll
            for (int j = 0; j < 8; j++) {
                float dist = fmaf(-2.0f, acc[i][j], __ldg(&g_csq[kb + c0 + j]));
                if (dist < b) { b = dist; bi = kb + c0 + j; }
            }
            atomicMin(&g_best[rows[r0 + i]], packdi(b, bi));
        }
    }
}

__global__ void writeback_kernel(float* __restrict__ out) {
    const int nf = g_nflag;
    for (int s = blockIdx.x * 256 + threadIdx.x; s < nf; s += 64 * 256) {
        int row = g_flag[s];
        out[row] = (float)(unsigned)(g_best[row] & 0xffffffffull);
    }
}

// ---------------- launch -----------------------------------------------------
extern "C" void kernel_launch(void* const* d_in, const int* in_sizes, int n_in,
                              void* d_out, int out_size) {
    const float* x      = (const float*)d_in[0];
    const float* center = (const float*)d_in[1];
    if (n_in >= 2 && in_sizes[0] < in_sizes[1]) {
        const float* tmp = x; x = center; center = tmp;
    }
    float* out = (float*)d_out;

    cudaFuncSetAttribute(kmeans_mma_kernel,
                         cudaFuncAttributeMaxDynamicSharedMemorySize, SMEM_DYN);

    cvt_c_kernel<<<(K_CL * (D_DIM / 4)) / 256, 256>>>(center);
    csq_kernel<<<K_CL, 128>>>(center);
    kmeans_mma_kernel<<<N_PTS / TM, 256, SMEM_DYN>>>(x, out);
    rescue_kernel<<<dim3(32, 64), 256>>>(x, center);
    writeback_kernel<<<64, 256>>>(out);
}